// round 1
// baseline (speedup 1.0000x reference)
#include <cuda_runtime.h>

// involution: out[b, g*64+c, h, w] = sum_{kh,kw} x[b, g*64+c, h+kh-3, w+kw-3] * wt[b,g,kh,kw,h,w]
// B=8, G=8, CPG=64, H=W=64, K=7, pad=3, stride=1.

#define NTHREADS 256
#define TH 8
#define ROWS 14          // TH + 6
#define SMW 72           // padded row stride (floats), even -> 8B-aligned pairs
#define TILE_ELEMS 980   // ROWS * 70

__device__ __forceinline__ unsigned long long pk2(float lo, float hi) {
    unsigned long long r;
    asm("mov.b64 %0, {%1, %2};" : "=l"(r) : "f"(lo), "f"(hi));
    return r;
}
__device__ __forceinline__ unsigned long long ffma2(unsigned long long a,
                                                    unsigned long long b,
                                                    unsigned long long c) {
    unsigned long long d;
    asm("fma.rn.f32x2 %0, %1, %2, %3;" : "=l"(d) : "l"(a), "l"(b), "l"(c));
    return d;
}
__device__ __forceinline__ float2 upk(unsigned long long v) {
    float2 r;
    asm("mov.b64 {%0, %1}, %2;" : "=f"(r.x), "=f"(r.y) : "l"(v));
    return r;
}

__global__ void __launch_bounds__(NTHREADS) involution_kernel(
    const float* __restrict__ x, const float* __restrict__ wt, float* __restrict__ out)
{
    __shared__ __align__(16) float sbuf[2][ROWS * SMW];

    const int tid = threadIdx.x;
    const int bid = blockIdx.x;
    const int ht = bid & 7;          // h tile
    const int g  = (bid >> 3) & 7;   // group
    const int b  = bid >> 6;         // batch
    const int h0 = ht * TH;
    const int u  = tid & 31;         // 32 lanes cover 64 w as pairs
    const int hy = tid >> 5;         // 0..7 output row within tile
    const int h  = h0 + hy;
    const int w0 = 2 * u;

    // ---- per-thread weights: 49 taps x 2 outputs, packed as f32x2 pairs.
    // even output (w0):   taps map to smem cols w0+0..w0+6 -> pairs P0..P3 (P3.hi unused -> weight 0)
    // odd  output (w0+1): taps map to smem cols w0+1..w0+7 -> P0.hi..P3   (P0.lo unused -> weight 0)
    const float* wb = wt + ((b * 8 + g) * 49) * 4096 + h * 64 + w0;
    unsigned long long WE[7][4], WO[7][4];
#pragma unroll
    for (int kh = 0; kh < 7; kh++) {
        float we[7], wo[7];
#pragma unroll
        for (int kw = 0; kw < 7; kw++) {
            float2 p = *(const float2*)(wb + (kh * 7 + kw) * 4096);
            we[kw] = p.x; wo[kw] = p.y;
        }
        WE[kh][0] = pk2(we[0], we[1]);
        WE[kh][1] = pk2(we[2], we[3]);
        WE[kh][2] = pk2(we[4], we[5]);
        WE[kh][3] = pk2(we[6], 0.0f);
        WO[kh][0] = pk2(0.0f, wo[0]);
        WO[kh][1] = pk2(wo[1], wo[2]);
        WO[kh][2] = pk2(wo[3], wo[4]);
        WO[kh][3] = pk2(wo[5], wo[6]);
    }

    // ---- tile-load offsets (invariant over channel loop)
    int soff[4], goff[4];
    bool ok[4];
#pragma unroll
    for (int k = 0; k < 4; k++) {
        int idx = tid + k * NTHREADS;
        int row = idx / 70;
        int col = idx - row * 70;
        int hh = h0 - 3 + row;       // global x row
        int ww = col - 3;            // global x col
        soff[k] = row * SMW + col;
        goff[k] = hh * 64 + ww;
        ok[k] = (idx < TILE_ELEMS) && (hh >= 0) && (hh < 64) && (ww >= 0) && (ww < 64);
    }

    const float* xg = x + ((b * 8 + g) * 64) * 4096;   // channel 0 of this (b,g)
    float* og = out + ((b * 8 + g) * 64) * 4096;

    // ---- prologue: load channel 0 into buffer 0
    float stg[4];
#pragma unroll
    for (int k = 0; k < 4; k++) stg[k] = ok[k] ? __ldg(xg + goff[k]) : 0.0f;
#pragma unroll
    for (int k = 0; k < 4; k++)
        if (tid + k * NTHREADS < TILE_ELEMS) sbuf[0][soff[k]] = stg[k];
    __syncthreads();

    // ---- channel loop, double-buffered, 1 barrier per iteration
#pragma unroll 2
    for (int c = 0; c < 64; c++) {
        if (c < 63) {
            const float* xn = xg + (c + 1) * 4096;
#pragma unroll
            for (int k = 0; k < 4; k++) stg[k] = ok[k] ? __ldg(xn + goff[k]) : 0.0f;
        }

        const float* sb = sbuf[c & 1] + hy * SMW + w0;
        unsigned long long ae = 0ULL, ao = 0ULL;
#pragma unroll
        for (int kh = 0; kh < 7; kh++) {
            const unsigned long long* r = (const unsigned long long*)(sb + kh * SMW);
            unsigned long long P0 = r[0];
            unsigned long long P1 = r[1];
            unsigned long long P2 = r[2];
            unsigned long long P3 = r[3];
            ae = ffma2(P0, WE[kh][0], ae);
            ao = ffma2(P0, WO[kh][0], ao);
            ae = ffma2(P1, WE[kh][1], ae);
            ao = ffma2(P1, WO[kh][1], ao);
            ae = ffma2(P2, WE[kh][2], ae);
            ao = ffma2(P2, WO[kh][2], ao);
            ae = ffma2(P3, WE[kh][3], ae);
            ao = ffma2(P3, WO[kh][3], ao);
        }
        float2 e = upk(ae);
        float2 o = upk(ao);
        *(float2*)(og + c * 4096 + h * 64 + w0) = make_float2(e.x + e.y, o.x + o.y);

        if (c < 63) {
            float* db = sbuf[(c + 1) & 1];
#pragma unroll
            for (int k = 0; k < 4; k++)
                if (tid + k * NTHREADS < TILE_ELEMS) db[soff[k]] = stg[k];
        }
        __syncthreads();
    }
}

extern "C" void kernel_launch(void* const* d_in, const int* in_sizes, int n_in,
                              void* d_out, int out_size) {
    const float* x  = (const float*)d_in[0];
    const float* wt = (const float*)d_in[1];
    // defensive: identify tensors by size (x: 8*512*64*64 = 16777216, w: 8*8*49*4096 = 12845056)
    if (n_in >= 2 && in_sizes[0] == 8 * 8 * 7 * 7 * 64 * 64) {
        const float* t = x; x = wt; wt = t;
    }
    float* out = (float*)d_out;
    involution_kernel<<<512, NTHREADS>>>(x, wt, out);
}

// round 2
// speedup vs baseline: 1.5591x; 1.5591x over previous
#include <cuda_runtime.h>

// involution: out[b, g*64+c, h, w] = sum_{kh,kw} x[b, g*64+c, h+kh-3, w+kw-3] * wt[b,g,kh,kw,h,w]
// B=8, G=8, CPG=64, H=W=64, K=7, pad=3, stride=1.

#define NTHREADS 256
#define TH 8
#define ROWS 14            // TH + 6
#define SMW 72             // padded row stride (floats)
#define TILE_ELEMS 980     // ROWS * 70
#define BUF_FLOATS 1008    // ROWS * SMW
#define NBUF 5
#define BUF_BYTES (BUF_FLOATS * 4)

__device__ __forceinline__ unsigned long long pk2(float lo, float hi) {
    unsigned long long r;
    asm("mov.b64 %0, {%1, %2};" : "=l"(r) : "f"(lo), "f"(hi));
    return r;
}
__device__ __forceinline__ unsigned long long ffma2(unsigned long long a,
                                                    unsigned long long b,
                                                    unsigned long long c) {
    unsigned long long d;
    asm("fma.rn.f32x2 %0, %1, %2, %3;" : "=l"(d) : "l"(a), "l"(b), "l"(c));
    return d;
}
__device__ __forceinline__ float f2lo(unsigned long long v) {
    float a, b;
    asm("mov.b64 {%0, %1}, %2;" : "=f"(a), "=f"(b) : "l"(v));
    return a;
}
__device__ __forceinline__ float f2hi(unsigned long long v) {
    float a, b;
    asm("mov.b64 {%0, %1}, %2;" : "=f"(a), "=f"(b) : "l"(v));
    return b;
}
__device__ __forceinline__ void cp_async4(unsigned dst, const void* src) {
    asm volatile("cp.async.ca.shared.global [%0], [%1], 4;" :: "r"(dst), "l"(src));
}
__device__ __forceinline__ void cp_commit() {
    asm volatile("cp.async.commit_group;");
}
__device__ __forceinline__ void cp_wait3() {
    asm volatile("cp.async.wait_group 3;");
}

__global__ void __launch_bounds__(NTHREADS, 2) involution_kernel(
    const float* __restrict__ x, const float* __restrict__ wt, float* __restrict__ out)
{
    __shared__ __align__(16) float sbuf[NBUF * BUF_FLOATS];

    const int tid = threadIdx.x;
    const int bid = blockIdx.x;
    const int ht = bid & 7;          // h tile
    const int g  = (bid >> 3) & 7;   // group
    const int b  = bid >> 6;         // batch
    const int h0 = ht * TH;
    const int u  = tid & 31;         // 32 lanes cover 64 w as pairs
    const int hy = tid >> 5;         // 0..7 output row within tile
    const int h  = h0 + hy;
    const int w0 = 2 * u;

    unsigned smem_base;
    {
        unsigned long long t;
        asm("cvta.to.shared.u64 %0, %1;" : "=l"(t) : "l"((const void*)sbuf));
        smem_base = (unsigned)t;
    }

    // ---- zero all buffers once (cp.async never writes OOB slots; they must stay 0)
    for (int i = tid; i < NBUF * BUF_FLOATS; i += NTHREADS) sbuf[i] = 0.0f;

    // ---- per-thread weights (tight packing, 98 regs):
    // even output (w0): P0*(we0,we1) + P1*(we2,we3) + P2*(we4,we5) + P3.lo*we6
    // odd  output     : P0.hi*wo0 + P1*(wo1,wo2) + P2*(wo3,wo4) + P3*(wo5,wo6)
    const float* wb = wt + ((b * 8 + g) * 49) * 4096 + h * 64 + w0;
    unsigned long long WE[7][3], WO[7][3];
    float WEs[7], WOs[7];
#pragma unroll
    for (int kh = 0; kh < 7; kh++) {
        float we[7], wo[7];
#pragma unroll
        for (int kw = 0; kw < 7; kw++) {
            float2 p = *(const float2*)(wb + (kh * 7 + kw) * 4096);
            we[kw] = p.x; wo[kw] = p.y;
        }
        WE[kh][0] = pk2(we[0], we[1]);
        WE[kh][1] = pk2(we[2], we[3]);
        WE[kh][2] = pk2(we[4], we[5]);
        WEs[kh]   = we[6];
        WO[kh][0] = pk2(wo[1], wo[2]);
        WO[kh][1] = pk2(wo[3], wo[4]);
        WO[kh][2] = pk2(wo[5], wo[6]);
        WOs[kh]   = wo[0];
    }

    // ---- tile-load offsets (invariant over channel loop)
    unsigned sdst[4];   // byte offset within a buffer
    int goff[4];        // element offset within a channel plane
    bool ok[4];
#pragma unroll
    for (int k = 0; k < 4; k++) {
        int idx = tid + k * NTHREADS;
        int row = idx / 70;
        int col = idx - row * 70;
        int hh = h0 - 3 + row;
        int ww = col - 3;
        sdst[k] = (unsigned)((row * SMW + col) * 4);
        goff[k] = hh * 64 + ww;
        ok[k] = (idx < TILE_ELEMS) && (hh >= 0) && (hh < 64) && (ww >= 0) && (ww < 64);
    }

    const float* xg = x + ((b * 8 + g) * 64) * 4096;
    float* og = out + ((b * 8 + g) * 64) * 4096 + h * 64 + w0;

    __syncthreads();   // buffers zeroed before any cp.async lands

    // ---- prologue: issue channels 0,1,2 (one commit group each)
#pragma unroll
    for (int pre = 0; pre < 3; pre++) {
        unsigned dbase = smem_base + pre * BUF_BYTES;
        const float* xs = xg + pre * 4096;
#pragma unroll
        for (int k = 0; k < 4; k++)
            if (ok[k]) cp_async4(dbase + sdst[k], xs + goff[k]);
        cp_commit();
    }

    unsigned load_base = smem_base + 3 * BUF_BYTES;   // buffer for channel c+3
    unsigned comp_base = smem_base;                   // buffer for channel c
    const float* xload = xg + 3 * 4096;

#pragma unroll 1
    for (int c = 0; c < 64; c++) {
        if (c < 61) {
#pragma unroll
            for (int k = 0; k < 4; k++)
                if (ok[k]) cp_async4(load_base + sdst[k], xload + goff[k]);
        }
        cp_commit();
        cp_wait3();
        __syncthreads();

        const float* sb = (const float*)(sbuf) + (comp_base - smem_base) / 4 + hy * SMW + w0;
        unsigned long long ae = 0ULL, ao = 0ULL;
        float se = 0.0f, so = 0.0f;
#pragma unroll
        for (int kh = 0; kh < 7; kh++) {
            const unsigned long long* r = (const unsigned long long*)(sb + kh * SMW);
            unsigned long long P0 = r[0];
            unsigned long long P1 = r[1];
            unsigned long long P2 = r[2];
            unsigned long long P3 = r[3];
            ae = ffma2(P0, WE[kh][0], ae);
            ao = ffma2(P1, WO[kh][0], ao);
            ae = ffma2(P1, WE[kh][1], ae);
            ao = ffma2(P2, WO[kh][1], ao);
            ae = ffma2(P2, WE[kh][2], ae);
            ao = ffma2(P3, WO[kh][2], ao);
            se = fmaf(f2lo(P3), WEs[kh], se);
            so = fmaf(f2hi(P0), WOs[kh], so);
        }
        float eo0 = f2lo(ae) + f2hi(ae) + se;
        float eo1 = f2lo(ao) + f2hi(ao) + so;
        *(float2*)og = make_float2(eo0, eo1);
        og += 4096;

        // advance rolling buffer pointers (mod 5)
        load_base += BUF_BYTES;
        if (load_base >= smem_base + NBUF * BUF_BYTES) load_base -= NBUF * BUF_BYTES;
        comp_base += BUF_BYTES;
        if (comp_base >= smem_base + NBUF * BUF_BYTES) comp_base -= NBUF * BUF_BYTES;
        xload += 4096;
    }
}

extern "C" void kernel_launch(void* const* d_in, const int* in_sizes, int n_in,
                              void* d_out, int out_size) {
    const float* x  = (const float*)d_in[0];
    const float* wt = (const float*)d_in[1];
    if (n_in >= 2 && in_sizes[0] == 8 * 8 * 7 * 7 * 64 * 64) {
        const float* t = x; x = wt; wt = t;
    }
    float* out = (float*)d_out;
    involution_kernel<<<512, NTHREADS>>>(x, wt, out);
}